// round 1
// baseline (speedup 1.0000x reference)
#include <cuda_runtime.h>
#include <cuda_bf16.h>

#define N_ATOMS 40000
#define N_PAIRS 640000
#define DD 128
#define RR 20

// Scratch (allocation-free rule: static device globals)
__device__ float g_h[N_ATOMS * DD];    // 20.48 MB
__device__ float g_agg[N_ATOMS * DD];  // 20.48 MB

__device__ __forceinline__ float sspf(float x) {
    // shifted softplus: log1p(exp(x)) - log(2), fast-math MUFU version.
    float sp = (x > 15.f) ? x : __logf(1.f + __expf(x));
    return sp - 0.69314718055994531f;
}

__global__ void zero_kernel(float4* __restrict__ p, int n4) {
    int i = blockIdx.x * blockDim.x + threadIdx.x;
    if (i < n4) p[i] = make_float4(0.f, 0.f, 0.f, 0.f);
}

// -----------------------------------------------------------------------------
// Tiled SGEMM: out[M,128] = A[M,128] @ W[128,128]^T + bias, optional ssp epilogue
// BM=64, BN=128, BK=16, 256 threads, 8x4 micro-tile per thread.
// -----------------------------------------------------------------------------
template <bool SSP>
__global__ __launch_bounds__(256) void gemm_atoms(
    const float* __restrict__ A, const float* __restrict__ W,
    const float* __restrict__ bias, float* __restrict__ out, int M)
{
    __shared__ float As[16][68];    // [k][row], padded
    __shared__ float Bs[16][132];   // [k][col], padded (132*4 = 528 bytes, 16B-aligned rows)

    const int tid  = threadIdx.x;
    const int tcol = tid & 31;      // covers cols 4*tcol .. 4*tcol+3
    const int trow = tid >> 5;      // covers rows 8*trow .. 8*trow+7
    const int a0   = blockIdx.x * 64;

    float acc[8][4];
#pragma unroll
    for (int i = 0; i < 8; i++)
#pragma unroll
        for (int j = 0; j < 4; j++) acc[i][j] = 0.f;

    for (int kt = 0; kt < 128; kt += 16) {
        // A tile: 64 rows x 16 k  (one float4 per thread)
        {
            int r = tid >> 2, kg = (tid & 3) << 2;
            float4 v = *(const float4*)&A[(size_t)(a0 + r) * 128 + kt + kg];
            As[kg + 0][r] = v.x; As[kg + 1][r] = v.y;
            As[kg + 2][r] = v.z; As[kg + 3][r] = v.w;
        }
        // W tile: 128 rows(c) x 16 k (two float4 per thread)
#pragma unroll
        for (int q = 0; q < 2; q++) {
            int idx = tid + q * 256;          // 0..511
            int c = idx >> 2, kg = (idx & 3) << 2;
            float4 v = *(const float4*)&W[(size_t)c * 128 + kt + kg];
            Bs[kg + 0][c] = v.x; Bs[kg + 1][c] = v.y;
            Bs[kg + 2][c] = v.z; Bs[kg + 3][c] = v.w;
        }
        __syncthreads();
#pragma unroll
        for (int k = 0; k < 16; k++) {
            float4 b  = *(const float4*)&Bs[k][tcol * 4];
            float4 a1 = *(const float4*)&As[k][trow * 8];
            float4 a2 = *(const float4*)&As[k][trow * 8 + 4];
            float ar[8] = {a1.x, a1.y, a1.z, a1.w, a2.x, a2.y, a2.z, a2.w};
            float br[4] = {b.x, b.y, b.z, b.w};
#pragma unroll
            for (int i = 0; i < 8; i++)
#pragma unroll
                for (int j = 0; j < 4; j++) acc[i][j] += ar[i] * br[j];
        }
        __syncthreads();
    }

    float4 bia = *(const float4*)&bias[tcol * 4];
#pragma unroll
    for (int i = 0; i < 8; i++) {
        float4 o;
        o.x = acc[i][0] + bia.x;
        o.y = acc[i][1] + bia.y;
        o.z = acc[i][2] + bia.z;
        o.w = acc[i][3] + bia.w;
        if (SSP) {
            o.x = sspf(o.x); o.y = sspf(o.y); o.z = sspf(o.z); o.w = sspf(o.w);
        }
        *(float4*)&out[(size_t)(a0 + trow * 8 + i) * 128 + tcol * 4] = o;
    }
}

// -----------------------------------------------------------------------------
// Fused pair kernel: Wij = ssp(f_ij @ W_f^T + b_f) * rcut;
//                    agg[idx_i] += h[idx_j] * Wij   (atomic scatter)
// 128 threads/block (1 thread = 1 filter channel). W_f row in registers.
// Pairs processed in chunks of 32 staged through shared memory.
// -----------------------------------------------------------------------------
__global__ __launch_bounds__(128) void pair_kernel(
    const float* __restrict__ f_ij, const int* __restrict__ idx_i,
    const int* __restrict__ idx_j, const float* __restrict__ rcut,
    const float* __restrict__ W_f, const float* __restrict__ b_f,
    const float* __restrict__ h, float* __restrict__ agg)
{
    __shared__ __align__(16) float sWf[DD * RR];   // 10 KB
    __shared__ __align__(16) float sF[32 * RR];    // 2.5 KB
    __shared__ float sR[32];
    __shared__ int   sI[32];
    __shared__ int   sJ[32];

    const int tid = threadIdx.x;   // channel c

    for (int i = tid; i < DD * RR; i += 128) sWf[i] = W_f[i];
    __syncthreads();

    float wreg[RR];
#pragma unroll
    for (int k = 0; k < RR; k++) wreg[k] = sWf[tid * RR + k];
    const float bf = b_f[tid];

    const int nchunks = N_PAIRS / 32;
    for (int ch = blockIdx.x; ch < nchunks; ch += gridDim.x) {
        const int base = ch * 32;
        __syncthreads();   // protect sF/sR/sI/sJ reuse
        {
            const float4* fsrc = (const float4*)&f_ij[(size_t)base * RR];
            float4* fdst = (float4*)sF;
            for (int i = tid; i < 160; i += 128) fdst[i] = fsrc[i];
            if (tid < 32) {
                sR[tid] = rcut[base + tid];
                sI[tid] = idx_i[base + tid];
                sJ[tid] = idx_j[base + tid];
            }
        }
        __syncthreads();

#pragma unroll 4
        for (int q = 0; q < 32; q++) {
            const float4* fq = (const float4*)&sF[q * RR];  // q*80 bytes, 16B-aligned
            float4 f0 = fq[0], f1 = fq[1], f2 = fq[2], f3 = fq[3], f4 = fq[4];
            float acc = bf;
            acc += f0.x * wreg[0];  acc += f0.y * wreg[1];
            acc += f0.z * wreg[2];  acc += f0.w * wreg[3];
            acc += f1.x * wreg[4];  acc += f1.y * wreg[5];
            acc += f1.z * wreg[6];  acc += f1.w * wreg[7];
            acc += f2.x * wreg[8];  acc += f2.y * wreg[9];
            acc += f2.z * wreg[10]; acc += f2.w * wreg[11];
            acc += f3.x * wreg[12]; acc += f3.y * wreg[13];
            acc += f3.z * wreg[14]; acc += f3.w * wreg[15];
            acc += f4.x * wreg[16]; acc += f4.y * wreg[17];
            acc += f4.z * wreg[18]; acc += f4.w * wreg[19];

            float w = sspf(acc) * sR[q];
            float hv = __ldg(&h[(size_t)sJ[q] * DD + tid]);
            atomicAdd(&agg[(size_t)sI[q] * DD + tid], hv * w);
        }
    }
}

extern "C" void kernel_launch(void* const* d_in, const int* in_sizes, int n_in,
                              void* d_out, int out_size)
{
    const float* x     = (const float*)d_in[0];
    const float* f_ij  = (const float*)d_in[1];
    const int*   idx_i = (const int*)d_in[2];
    const int*   idx_j = (const int*)d_in[3];
    const float* rcut  = (const float*)d_in[4];
    const float* W_in  = (const float*)d_in[5];
    const float* b_in  = (const float*)d_in[6];
    const float* W_f   = (const float*)d_in[7];
    const float* b_f   = (const float*)d_in[8];
    const float* W_out = (const float*)d_in[9];
    const float* b_out = (const float*)d_in[10];
    float* out = (float*)d_out;

    float* hptr = nullptr;
    float* aptr = nullptr;
    cudaGetSymbolAddress((void**)&hptr, g_h);
    cudaGetSymbolAddress((void**)&aptr, g_agg);

    const int n4 = N_ATOMS * DD / 4;
    zero_kernel<<<(n4 + 255) / 256, 256>>>((float4*)aptr, n4);
    gemm_atoms<false><<<N_ATOMS / 64, 256>>>(x, W_in, b_in, hptr, N_ATOMS);
    pair_kernel<<<2048, 128>>>(f_ij, idx_i, idx_j, rcut, W_f, b_f, hptr, aptr);
    gemm_atoms<true><<<N_ATOMS / 64, 256>>>(aptr, W_out, b_out, out, N_ATOMS);
}